// round 13
// baseline (speedup 1.0000x reference)
#include <cuda_runtime.h>
#include <math.h>

#define NCTA   128
#define NTHR   256
#define NWRP   8
#define HID    1024
#define GATES  4096
#define LATENT 2048
#define SEQ    16
// smem: wbuf 32K floats (x staging / w_hh slice / h1 staging, time-shared)
//       + hstage 1K floats (per-step h broadcast)
#define SMEM_FLOATS (32 * 1024 + 1024)
#define SMEM_BYTES  (SMEM_FLOATS * 4)   // 132KB -> 1 CTA/SM

// ---------------- device scratch (no allocation allowed) ----------------
__device__ float g_xg[SEQ * GATES];   // gate pre-activations, current layer
__device__ float g_h1[SEQ * HID];     // layer-0 hidden outputs (per-step rows)
__device__ __align__(128) unsigned g_bar_line[32];
#define g_bar (g_bar_line[0])

// ---- grid barrier: flip-bit; release-RMW arrival, relaxed busy-poll,
// one acquire fence after detection (strong ops stay off the hot line) ----
__device__ __forceinline__ void grid_barrier() {
    __syncthreads();
    if (threadIdx.x == 0) {
        unsigned nb = (blockIdx.x == 0) ? (0x80000000u - (NCTA - 1u)) : 1u;
        unsigned old;
        asm volatile("atom.add.release.gpu.global.u32 %0, [%1], %2;"
                     : "=r"(old) : "l"(&g_bar), "r"(nb) : "memory");
        unsigned cur;
        do {
            asm volatile("ld.relaxed.gpu.global.u32 %0, [%1];"
                         : "=r"(cur) : "l"(&g_bar) : "memory");
        } while (((old ^ cur) & 0x80000000u) == 0u);
        asm volatile("fence.acq_rel.gpu;" ::: "memory");
    }
    __syncthreads();
}

__device__ __forceinline__ float sigmoidf_(float x) {
    return 1.0f / (1.0f + __expf(-x));
}
__device__ __forceinline__ float tanhf_fast(float x) {   // R9-validated
    return 2.0f / (1.0f + __expf(-2.0f * x)) - 1.0f;
}

// L1-bypassing accessors for cross-CTA mutable data
__device__ __forceinline__ float4 ldcg4(const float4* p) {
    float4 v;
    asm volatile("ld.global.cg.v4.f32 {%0,%1,%2,%3}, [%4];"
                 : "=f"(v.x), "=f"(v.y), "=f"(v.z), "=f"(v.w) : "l"(p) : "memory");
    return v;
}
__device__ __forceinline__ float ldcg1(const float* p) {
    float v;
    asm volatile("ld.global.cg.f32 %0, [%1];" : "=f"(v) : "l"(p) : "memory");
    return v;
}
__device__ __forceinline__ void stcg1(float* p, float v) {
    asm volatile("st.global.cg.f32 [%0], %1;" :: "l"(p), "f"(v) : "memory");
}

// ---------------- input GEMM phase (R6-verbatim arithmetic) -----------------
// out[t][row] = inp[t].W[row] + b1 + b2; warp gw owns rows 4gw..4gw+3.
// inp is ALWAYS staged into SMEM (one coalesced pass per CTA) so the inner
// loop never re-reads it through L2 (1024 warps x 128KB was ~12us of L2).
// MUTABLE: stage via ld.cg (cross-CTA-written); else plain loads (immutable x).
template <int D, bool MUTABLE>
__device__ void gate_gemm_dev(const float* __restrict__ W,
                              const float* __restrict__ inp,
                              const float* __restrict__ b1,
                              const float* __restrict__ b2,
                              float* __restrict__ out,
                              float* smem) {
    const int tid  = threadIdx.x;
    const int lane = tid & 31;
    const int warp = tid >> 5;
    const int NF4  = D / 4;

    {
        const float4* in4 = (const float4*)inp;
        float4* s4 = (float4*)smem;
        for (int i = tid; i < SEQ * D / 4; i += NTHR)
            s4[i] = MUTABLE ? ldcg4(&in4[i]) : in4[i];
    }
    __syncthreads();
    const float4* xs4 = (const float4*)smem;

    const int row = (blockIdx.x * NWRP + warp) * 4;   // 128*8 warps == GATES/4

    float acc[4][SEQ];
#pragma unroll
    for (int r = 0; r < 4; r++)
#pragma unroll
        for (int t = 0; t < SEQ; t++) acc[r][t] = 0.0f;

    const float4* w0 = (const float4*)(W + (size_t)(row + 0) * D);
    const float4* w1 = (const float4*)(W + (size_t)(row + 1) * D);
    const float4* w2 = (const float4*)(W + (size_t)(row + 2) * D);
    const float4* w3 = (const float4*)(W + (size_t)(row + 3) * D);

    for (int ci = lane; ci < NF4; ci += 32) {
        float4 a0 = w0[ci], a1 = w1[ci], a2 = w2[ci], a3 = w3[ci];
#pragma unroll
        for (int t = 0; t < SEQ; t++) {
            float4 xv = xs4[t * NF4 + ci];
            acc[0][t] += a0.x * xv.x + a0.y * xv.y + a0.z * xv.z + a0.w * xv.w;
            acc[1][t] += a1.x * xv.x + a1.y * xv.y + a1.z * xv.z + a1.w * xv.w;
            acc[2][t] += a2.x * xv.x + a2.y * xv.y + a2.z * xv.z + a2.w * xv.w;
            acc[3][t] += a3.x * xv.x + a3.y * xv.y + a3.z * xv.z + a3.w * xv.w;
        }
    }
#pragma unroll
    for (int r = 0; r < 4; r++) {
#pragma unroll
        for (int t = 0; t < SEQ; t++) {
            float s = acc[r][t];
#pragma unroll
            for (int off = 16; off; off >>= 1)
                s += __shfl_xor_sync(0xffffffffu, s, off);
            if (lane == 0)
                stcg1(&out[t * GATES + row + r], s + b1[row + r] + b2[row + r]);
        }
    }
}

// ---------------- one LSTM layer: SMEM weights + per-CTA h staging ----------
// CTA owns units j = blockIdx*8 + warp; its 32 gate rows (128KB fp32) live in
// SMEM for the whole layer (immune to the barrier fence's L1 invalidation).
// Per step: CTA stages h_{t-1} (4KB) ONCE from L2 (kills the 1024-warps-on-32-
// lines LTS serialization), syncthreads, warps read h via LDS, GEMV from SMEM,
// shuffle reduce, lane-0 pointwise (fast tanh), st.cg publish, barrier.
__device__ void lstm_layer_dev(const float* __restrict__ whh,
                               const float* __restrict__ xg,
                               float* __restrict__ hbase,     // SEQ rows out
                               float* __restrict__ last_out,  // null or HID
                               float* wbuf, float* hstage) {
    const int tid  = threadIdx.x;
    const int lane = tid & 31;
    const int warp = tid >> 5;
    const int base = blockIdx.x * NWRP;
    const int j    = base + warp;

    // stage w_hh slice (float4): smem row r = w*4+g <-> global row g*HID+(base+w)
    {
        float4* wb4 = (float4*)wbuf;
        for (int idx4 = tid; idx4 < 32 * HID / 4; idx4 += NTHR) {
            int r = idx4 >> 8, k4 = idx4 & 255;
            int w = r >> 2, g = r & 3;
            wb4[idx4] = ((const float4*)(whh + (size_t)(g * HID + base + w) * HID))[k4];
        }
    }

    // preload this unit's 4 gate biases for all 16 steps: lane t holds step t
    float xgi = 0.f, xgf = 0.f, xgg = 0.f, xgo = 0.f;
    if (lane < SEQ) {
        const float* xgt = xg + lane * GATES;
        xgi = ldcg1(&xgt[0 * HID + j]);
        xgf = ldcg1(&xgt[1 * HID + j]);
        xgg = ldcg1(&xgt[2 * HID + j]);
        xgo = ldcg1(&xgt[3 * HID + j]);
    }
    __syncthreads();

    const float4* w0 = (const float4*)(wbuf + (warp * 4 + 0) * HID);
    const float4* w1 = (const float4*)(wbuf + (warp * 4 + 1) * HID);
    const float4* w2 = (const float4*)(wbuf + (warp * 4 + 2) * HID);
    const float4* w3 = (const float4*)(wbuf + (warp * 4 + 3) * HID);
    float4* hs4 = (float4*)hstage;

    float c = 0.0f;
    for (int t = 0; t < SEQ; t++) {
        float dot[4] = {0.f, 0.f, 0.f, 0.f};
        if (t > 0) {
            // CTA-wide single staging pass of h_{t-1} (WAR on hstage protected
            // by the previous iteration's barrier syncthreads)
            const float4* hp4 = (const float4*)(hbase + (t - 1) * HID);
            for (int i = tid; i < HID / 4; i += NTHR) hs4[i] = ldcg4(&hp4[i]);
            __syncthreads();

            float4 hv[8];
#pragma unroll
            for (int q = 0; q < 8; q++) hv[q] = hs4[lane + 32 * q];

            float s0 = 0.f, s1 = 0.f, s2 = 0.f, s3 = 0.f;
#pragma unroll
            for (int q = 0; q < 8; q++) {
                float4 a0 = w0[lane + 32 * q];
                float4 a1 = w1[lane + 32 * q];
                float4 a2 = w2[lane + 32 * q];
                float4 a3 = w3[lane + 32 * q];
                s0 += a0.x * hv[q].x + a0.y * hv[q].y + a0.z * hv[q].z + a0.w * hv[q].w;
                s1 += a1.x * hv[q].x + a1.y * hv[q].y + a1.z * hv[q].z + a1.w * hv[q].w;
                s2 += a2.x * hv[q].x + a2.y * hv[q].y + a2.z * hv[q].z + a2.w * hv[q].w;
                s3 += a3.x * hv[q].x + a3.y * hv[q].y + a3.z * hv[q].z + a3.w * hv[q].w;
            }
            dot[0] = s0; dot[1] = s1; dot[2] = s2; dot[3] = s3;
#pragma unroll
            for (int g = 0; g < 4; g++)
#pragma unroll
                for (int off = 16; off; off >>= 1)
                    dot[g] += __shfl_xor_sync(0xffffffffu, dot[g], off);
        }

        // step-t biases by shuffle from lane t (all lanes converged here)
        float bi = __shfl_sync(0xffffffffu, xgi, t);
        float bf = __shfl_sync(0xffffffffu, xgf, t);
        float bg = __shfl_sync(0xffffffffu, xgg, t);
        float bo = __shfl_sync(0xffffffffu, xgo, t);

        if (lane == 0) {
            float iv = sigmoidf_(bi + dot[0]);
            float fv = sigmoidf_(bf + dot[1]);
            float gv = tanhf_fast(bg + dot[2]);
            float ov = sigmoidf_(bo + dot[3]);
            float cn = fv * c + iv * gv;
            c = cn;
            float hval = ov * tanhf_fast(cn);
            stcg1(&hbase[t * HID + j], hval);
            if (last_out && t == SEQ - 1) stcg1(&last_out[j], hval);
        }
        // publish h_t; very last step of the final layer needs no barrier
        if (!(last_out && t == SEQ - 1)) grid_barrier();
    }
}

// ---------------- single persistent kernel ----------------------------------
__global__ void __launch_bounds__(NTHR, 1)
lstm2_persist(const float* __restrict__ x,
              const float* __restrict__ w_ih0, const float* __restrict__ w_hh0,
              const float* __restrict__ b_ih0, const float* __restrict__ b_hh0,
              const float* __restrict__ w_ih1, const float* __restrict__ w_hh1,
              const float* __restrict__ b_ih1, const float* __restrict__ b_hh1,
              float* __restrict__ out) {
    extern __shared__ float smem[];
    float* wbuf   = smem;                // 32K floats, time-shared
    float* hstage = smem + 32 * 1024;    // 1K floats

    // Phase A: xg = x @ w_ih0^T + b_ih0 + b_hh0 (x staged: immutable, plain)
    gate_gemm_dev<LATENT, false>(w_ih0, x, b_ih0, b_hh0, g_xg, wbuf);
    grid_barrier();

    // Layer 0 recurrence (w_hh0 SMEM-resident; last barrier orders g_h1)
    lstm_layer_dev(w_hh0, g_xg, g_h1, nullptr, wbuf, hstage);

    // Phase C: xg = h1 @ w_ih1^T + b_ih1 + b_hh1 (h1 staged via ld.cg)
    gate_gemm_dev<HID, true>(w_ih1, g_h1, b_ih1, b_hh1, g_xg, wbuf);
    grid_barrier();

    // Layer 1 recurrence -> out: [0:HID) last_output, [HID:) h2 rows
    lstm_layer_dev(w_hh1, g_xg, out + HID, out, wbuf, hstage);
}

// ---------------- host launch (graph-capturable, single node) ---------------
extern "C" void kernel_launch(void* const* d_in, const int* in_sizes, int n_in,
                              void* d_out, int out_size) {
    const float* x     = (const float*)d_in[0];
    const float* w_ih0 = (const float*)d_in[1];
    const float* w_hh0 = (const float*)d_in[2];
    const float* b_ih0 = (const float*)d_in[3];
    const float* b_hh0 = (const float*)d_in[4];
    const float* w_ih1 = (const float*)d_in[5];
    const float* w_hh1 = (const float*)d_in[6];
    const float* b_ih1 = (const float*)d_in[7];
    const float* b_hh1 = (const float*)d_in[8];
    float* out = (float*)d_out;

    cudaFuncSetAttribute(lstm2_persist,
                         cudaFuncAttributeMaxDynamicSharedMemorySize, SMEM_BYTES);
    lstm2_persist<<<NCTA, NTHR, SMEM_BYTES>>>(x, w_ih0, w_hh0, b_ih0, b_hh0,
                                              w_ih1, w_hh1, b_ih1, b_hh1, out);
}

// round 15
// speedup vs baseline: 1.2139x; 1.2139x over previous
#include <cuda_runtime.h>
#include <math.h>

#define NCTA   128
#define NTHR   512
#define HID    1024
#define GATES  4096
#define LATENT 2048
#define SEQ    16

// smem: GEMM input staging (SEQ*LATENT fp32 = 128KB, largest use)
//       + hstage 1K floats + xgbuf 512 floats + gdot 32 floats
#define SMEM_STAGE_FLOATS (SEQ * LATENT)
#define SMEM_FLOATS (SMEM_STAGE_FLOATS + 1024 + 512 + 32)
#define SMEM_BYTES  (SMEM_FLOATS * 4)   // ~134KB -> 1 CTA/SM

// ---------------- device scratch (no allocation allowed) ----------------
__device__ float g_xg[SEQ * GATES];   // gate pre-activations, current layer
__device__ float g_h1[SEQ * HID];     // layer-0 hidden outputs (per-step rows)
__device__ __align__(128) unsigned g_bar_line[32];
#define g_bar (g_bar_line[0])

// ---- grid barrier: R12-verbatim (PROVEN). flip-bit; release-RMW arrival,
// relaxed poll, one acquire fence after detection. --------------------------
__device__ __forceinline__ void grid_barrier() {
    __syncthreads();
    if (threadIdx.x == 0) {
        unsigned nb = (blockIdx.x == 0) ? (0x80000000u - (NCTA - 1u)) : 1u;
        unsigned old;
        asm volatile("atom.add.release.gpu.global.u32 %0, [%1], %2;"
                     : "=r"(old) : "l"(&g_bar), "r"(nb) : "memory");
        unsigned cur;
        do {
            asm volatile("ld.relaxed.gpu.global.u32 %0, [%1];"
                         : "=r"(cur) : "l"(&g_bar) : "memory");
        } while (((old ^ cur) & 0x80000000u) == 0u);
        asm volatile("fence.acq_rel.gpu;" ::: "memory");
    }
    __syncthreads();
}

__device__ __forceinline__ float sigmoidf_(float x) {
    return 1.0f / (1.0f + __expf(-x));
}

// L1-bypassing accessors for cross-CTA mutable data
__device__ __forceinline__ float4 ldcg4(const float4* p) {
    float4 v;
    asm volatile("ld.global.cg.v4.f32 {%0,%1,%2,%3}, [%4];"
                 : "=f"(v.x), "=f"(v.y), "=f"(v.z), "=f"(v.w) : "l"(p) : "memory");
    return v;
}
__device__ __forceinline__ float ldcg1(const float* p) {
    float v;
    asm volatile("ld.global.cg.f32 %0, [%1];" : "=f"(v) : "l"(p) : "memory");
    return v;
}
__device__ __forceinline__ void stcg1(float* p, float v) {
    asm volatile("st.global.cg.f32 [%0], %1;" :: "l"(p), "f"(v) : "memory");
}

// ---------------- input GEMM phase -------------------------------------------
// out[t][row] = inp[t].W[row] + b1 + b2. 16 warps/CTA: warp PAIR (warp>>1)
// owns rows 4*(bid*8 + (warp>>1)) .. +3; warp&1 selects t half [0,8) or [8,16).
// Per-(row,t) accumulation order identical to R12 -> bit-identical results.
template <int D, bool MUTABLE>
__device__ void gate_gemm_dev(const float* __restrict__ W,
                              const float* __restrict__ inp,
                              const float* __restrict__ b1,
                              const float* __restrict__ b2,
                              float* __restrict__ out,
                              float* smem) {
    const int tid  = threadIdx.x;
    const int lane = tid & 31;
    const int warp = tid >> 5;
    const int NF4  = D / 4;

    {
        const float4* in4 = (const float4*)inp;
        float4* s4 = (float4*)smem;
        for (int i = tid; i < SEQ * D / 4; i += NTHR)
            s4[i] = MUTABLE ? ldcg4(&in4[i]) : in4[i];
    }
    __syncthreads();
    const float4* xs4 = (const float4*)smem;

    const int row = (blockIdx.x * 8 + (warp >> 1)) * 4;  // 128*8 pairs == GATES/4
    const int t0  = (warp & 1) * 8;

    float acc[4][8];
#pragma unroll
    for (int r = 0; r < 4; r++)
#pragma unroll
        for (int tt = 0; tt < 8; tt++) acc[r][tt] = 0.0f;

    const float4* w0 = (const float4*)(W + (size_t)(row + 0) * D);
    const float4* w1 = (const float4*)(W + (size_t)(row + 1) * D);
    const float4* w2 = (const float4*)(W + (size_t)(row + 2) * D);
    const float4* w3 = (const float4*)(W + (size_t)(row + 3) * D);

    for (int ci = lane; ci < NF4; ci += 32) {
        float4 a0 = w0[ci], a1 = w1[ci], a2 = w2[ci], a3 = w3[ci];
#pragma unroll
        for (int tt = 0; tt < 8; tt++) {
            float4 xv = xs4[(t0 + tt) * NF4 + ci];
            acc[0][tt] += a0.x * xv.x + a0.y * xv.y + a0.z * xv.z + a0.w * xv.w;
            acc[1][tt] += a1.x * xv.x + a1.y * xv.y + a1.z * xv.z + a1.w * xv.w;
            acc[2][tt] += a2.x * xv.x + a2.y * xv.y + a2.z * xv.z + a2.w * xv.w;
            acc[3][tt] += a3.x * xv.x + a3.y * xv.y + a3.z * xv.z + a3.w * xv.w;
        }
    }
#pragma unroll
    for (int r = 0; r < 4; r++) {
#pragma unroll
        for (int tt = 0; tt < 8; tt++) {
            float s = acc[r][tt];
#pragma unroll
            for (int off = 16; off; off >>= 1)
                s += __shfl_xor_sync(0xffffffffu, s, off);
            if (lane == 0)
                stcg1(&out[(t0 + tt) * GATES + row + r],
                      s + b1[row + r] + b2[row + r]);
        }
    }
}

// ---------------- one LSTM layer: REGISTER-resident weights -----------------
// CTA owns units base..base+7. Warp w: unit u = w>>1, gates gpair = (w&1)*2
// + {0,1}. Each lane holds its weight slice (16 float4 = 64 regs) for the
// whole layer -> per-step GEMV does ZERO weight loads. Per step: CTA stages
// h_{t-1} (4KB) once, LDS h, reg-FMA, shuffle reduce, gdot via SMEM, warp-0
// lanes 0..7 do pointwise (c in registers), st.cg publish, barrier.
__device__ void lstm_layer_dev(const float* __restrict__ whh,
                               const float* __restrict__ xg,
                               float* __restrict__ hbase,     // SEQ rows out
                               float* __restrict__ last_out,  // null or HID
                               float* hstage, float* xgbuf, float* gdot) {
    const int tid   = threadIdx.x;
    const int lane  = tid & 31;
    const int warp  = tid >> 5;
    const int base  = blockIdx.x * 8;
    const int u     = warp >> 1;
    const int gpair = (warp & 1) * 2;
    const int j     = base + u;

    // load this warp's 2 gate rows into registers (coalesced, once per layer)
    float4 wr0[8], wr1[8];
    {
        const float4* p0 = (const float4*)(whh + (size_t)((gpair + 0) * HID + j) * HID);
        const float4* p1 = (const float4*)(whh + (size_t)((gpair + 1) * HID + j) * HID);
#pragma unroll
        for (int q = 0; q < 8; q++) { wr0[q] = p0[lane + 32 * q]; wr1[q] = p1[lane + 32 * q]; }
    }

    // stage this CTA's gate biases for all steps: xgbuf[t*32 + uu*4 + g]
    for (int idx = tid; idx < SEQ * 32; idx += NTHR) {
        int t = idx >> 5, r = idx & 31;
        int uu = r >> 2, g = r & 3;
        xgbuf[idx] = ldcg1(&xg[t * GATES + g * HID + base + uu]);
    }
    __syncthreads();

    float c = 0.0f;
    float4* hs4 = (float4*)hstage;

    for (int t = 0; t < SEQ; t++) {
        if (t > 0) {
            // CTA-wide single staging pass of h_{t-1} (WAR protected by the
            // previous iteration's barrier syncthreads)
            const float4* hp4 = (const float4*)(hbase + (t - 1) * HID);
            for (int i = tid; i < HID / 4; i += NTHR) hs4[i] = ldcg4(&hp4[i]);
            __syncthreads();

            float s0 = 0.f, s1 = 0.f;
#pragma unroll
            for (int q = 0; q < 8; q++) {
                float4 h = hs4[lane + 32 * q];
                s0 += wr0[q].x * h.x + wr0[q].y * h.y + wr0[q].z * h.z + wr0[q].w * h.w;
                s1 += wr1[q].x * h.x + wr1[q].y * h.y + wr1[q].z * h.z + wr1[q].w * h.w;
            }
#pragma unroll
            for (int off = 16; off; off >>= 1) {
                s0 += __shfl_xor_sync(0xffffffffu, s0, off);
                s1 += __shfl_xor_sync(0xffffffffu, s1, off);
            }
            if (lane == 0) {
                gdot[u * 4 + gpair + 0] = s0;
                gdot[u * 4 + gpair + 1] = s1;
            }
            __syncthreads();
        }

        if (warp == 0 && lane < 8) {
            const int uu = lane;
            float d0 = 0.f, d1 = 0.f, d2 = 0.f, d3 = 0.f;
            if (t > 0) {
                d0 = gdot[uu * 4 + 0]; d1 = gdot[uu * 4 + 1];
                d2 = gdot[uu * 4 + 2]; d3 = gdot[uu * 4 + 3];
            }
            const float* xb = xgbuf + t * 32 + uu * 4;
            float iv = sigmoidf_(xb[0] + d0);
            float fv = sigmoidf_(xb[1] + d1);
            float gv = tanhf(xb[2] + d2);
            float ov = sigmoidf_(xb[3] + d3);
            float cn = fv * c + iv * gv;
            c = cn;
            float hval = ov * tanhf(cn);
            stcg1(&hbase[t * HID + base + uu], hval);
            if (last_out && t == SEQ - 1) stcg1(&last_out[base + uu], hval);
        }
        // publish h_t; very last step of the final layer needs no barrier
        if (!(last_out && t == SEQ - 1)) grid_barrier();
    }
}

// ---------------- single persistent kernel ----------------------------------
__global__ void __launch_bounds__(NTHR, 1)
lstm2_persist(const float* __restrict__ x,
              const float* __restrict__ w_ih0, const float* __restrict__ w_hh0,
              const float* __restrict__ b_ih0, const float* __restrict__ b_hh0,
              const float* __restrict__ w_ih1, const float* __restrict__ w_hh1,
              const float* __restrict__ b_ih1, const float* __restrict__ b_hh1,
              float* __restrict__ out) {
    extern __shared__ float smem[];
    float* stage  = smem;                            // 32K floats (GEMM staging)
    float* hstage = smem + SMEM_STAGE_FLOATS;        // 1K floats
    float* xgbuf  = hstage + 1024;                   // 512 floats
    float* gdot   = xgbuf + 512;                     // 32 floats

    // Phase A: xg = x @ w_ih0^T + b_ih0 + b_hh0   (x immutable -> plain LDG)
    gate_gemm_dev<LATENT, false>(w_ih0, x, b_ih0, b_hh0, g_xg, stage);
    grid_barrier();

    // Layer 0 recurrence (weights in registers; last barrier orders g_h1)
    lstm_layer_dev(w_hh0, g_xg, g_h1, nullptr, hstage, xgbuf, gdot);

    // Phase C: xg = h1 @ w_ih1^T + b_ih1 + b_hh1 (h1 mutable -> ld.cg staging)
    gate_gemm_dev<HID, true>(w_ih1, g_h1, b_ih1, b_hh1, g_xg, stage);
    grid_barrier();

    // Layer 1 recurrence -> out: [0:HID) last_output, [HID:) h2 rows
    lstm_layer_dev(w_hh1, g_xg, out + HID, out, hstage, xgbuf, gdot);
}

// ---------------- host launch (graph-capturable, single node) ---------------
extern "C" void kernel_launch(void* const* d_in, const int* in_sizes, int n_in,
                              void* d_out, int out_size) {
    const float* x     = (const float*)d_in[0];
    const float* w_ih0 = (const float*)d_in[1];
    const float* w_hh0 = (const float*)d_in[2];
    const float* b_ih0 = (const float*)d_in[3];
    const float* b_hh0 = (const float*)d_in[4];
    const float* w_ih1 = (const float*)d_in[5];
    const float* w_hh1 = (const float*)d_in[6];
    const float* b_ih1 = (const float*)d_in[7];
    const float* b_hh1 = (const float*)d_in[8];
    float* out = (float*)d_out;

    cudaFuncSetAttribute(lstm2_persist,
                         cudaFuncAttributeMaxDynamicSharedMemorySize, SMEM_BYTES);
    lstm2_persist<<<NCTA, NTHR, SMEM_BYTES>>>(x, w_ih0, w_hh0, b_ih0, b_hh0,
                                              w_ih1, w_hh1, b_ih1, b_hh1, out);
}